// round 11
// baseline (speedup 1.0000x reference)
#include <cuda_runtime.h>
#include <cuda_fp16.h>
#include <cstdint>

#define N_TOK 8192
#define DIM   1024
#define NEXP  8
#define HID   256

#define BM 128
#define BK 32    // K elements per tile (2 x k16 mma steps)
#define LDA 40   // padded row stride in halves: 80B, conflict-free ldmatrix
#define LDB 40
#define LDH1 264 // h1 smem row stride in halves: 528B (132 words, %32=4) conflict-free

// ---- static device scratch (no allocations allowed) ----
__device__ int    g_cursor[NEXP];
__device__ int    g_token[NEXP * N_TOK];
__device__ float  g_gate [NEXP * N_TOK];
__device__ int    g_slot [2 * N_TOK];
__device__ __half g_h2h[(size_t)NEXP * N_TOK * HID];   // 32 MB
__device__ __half g_eoh[(size_t)NEXP * N_TOK * DIM];   // 128 MB (sparse-touched)
__device__ __half g_w1t[(size_t)NEXP * DIM * HID];     // 4 MB  [e][N][K] half
__device__ __half g_w2t[(size_t)NEXP * HID * HID];     // 1 MB
__device__ __half g_w3t[(size_t)NEXP * HID * DIM];     // 4 MB

// ---------------------------------------------------------------------------
__device__ __forceinline__ void ldsm_x4(unsigned addr, unsigned r[4]) {
    asm volatile("ldmatrix.sync.aligned.m8n8.x4.shared.b16 {%0,%1,%2,%3}, [%4];"
                 : "=r"(r[0]), "=r"(r[1]), "=r"(r[2]), "=r"(r[3]) : "r"(addr));
}
__device__ __forceinline__ void mma_f16(float c[4], const unsigned a[4],
                                        unsigned b0, unsigned b1) {
    asm volatile(
        "mma.sync.aligned.m16n8k16.row.col.f32.f16.f16.f32 "
        "{%0,%1,%2,%3}, {%4,%5,%6,%7}, {%8,%9}, {%0,%1,%2,%3};"
        : "+f"(c[0]), "+f"(c[1]), "+f"(c[2]), "+f"(c[3])
        : "r"(a[0]), "r"(a[1]), "r"(a[2]), "r"(a[3]), "r"(b0), "r"(b1));
}
__device__ __forceinline__ unsigned pack_h2(float x, float y) {
    __half2 h = __floats2half2_rn(x, y);
    return *(unsigned*)&h;
}
__device__ __forceinline__ unsigned s2u(const void* p) {
    return (unsigned)__cvta_generic_to_shared(p);
}

// ---------------------------------------------------------------------------
// prep: zero cursors + transpose/convert all three weight tensors to [e][N][K] half
// grid (288, 1, 8): blocks 0..127 -> W1 (16x8 tiles), 128..159 -> W2 (4x8),
//                   160..287 -> W3 (4x32). Each block: 64k x 32n tile.
// ---------------------------------------------------------------------------
__global__ void prep_kernel(const float* __restrict__ W1,
                            const float* __restrict__ W2,
                            const float* __restrict__ W3,
                            __half* __restrict__ w1t,
                            __half* __restrict__ w2t,
                            __half* __restrict__ w3t) {
    if (blockIdx.x == 0 && blockIdx.z == 0 && threadIdx.x < NEXP)
        g_cursor[threadIdx.x] = 0;

    int e = blockIdx.z;
    int bid = blockIdx.x;
    const float* src;
    __half* dst;
    int KD, ND, kt, nt;
    if (bid < 128) {
        src = W1 + (size_t)e * DIM * HID; dst = w1t + (size_t)e * DIM * HID;
        KD = DIM; ND = HID; kt = bid >> 3; nt = bid & 7;
    } else if (bid < 160) {
        int r = bid - 128;
        src = W2 + (size_t)e * HID * HID; dst = w2t + (size_t)e * HID * HID;
        KD = HID; ND = HID; kt = r >> 3; nt = r & 7;
    } else {
        int r = bid - 160;
        src = W3 + (size_t)e * HID * DIM; dst = w3t + (size_t)e * HID * DIM;
        KD = HID; ND = DIM; kt = r >> 5; nt = r & 31;
    }

    __shared__ float tile[64][33];
    int tx = threadIdx.x & 31, ty = threadIdx.x >> 5;
    int k0 = kt * 64, n0 = nt * 32;
#pragma unroll
    for (int kr = ty; kr < 64; kr += 8)
        tile[kr][tx] = src[(size_t)(k0 + kr) * ND + n0 + tx];
    __syncthreads();
#pragma unroll
    for (int nr = ty; nr < 32; nr += 8) {
        __half2 hv = __floats2half2_rn(tile[2 * tx][nr], tile[2 * tx + 1][nr]);
        *(__half2*)(dst + (size_t)(n0 + nr) * KD + k0 + 2 * tx) = hv;
    }
}

// ---------------------------------------------------------------------------
// gating: one warp per token (uses ORIGINAL fp32 x)
// ---------------------------------------------------------------------------
__global__ void gating_kernel(const float* __restrict__ x,
                              const float* __restrict__ Wg,
                              const float* __restrict__ bg) {
    int warp = threadIdx.x >> 5;
    int lane = threadIdx.x & 31;
    int n = blockIdx.x * 8 + warp;
    if (n >= N_TOK) return;

    float acc[NEXP];
#pragma unroll
    for (int e = 0; e < NEXP; e++) acc[e] = 0.f;

    const float* xr = x + (size_t)n * DIM;
    for (int d = lane; d < DIM; d += 32) {
        float xv = xr[d];
        const float4* w4 = (const float4*)(Wg + (size_t)d * NEXP);
        float4 wa = w4[0];
        float4 wb = w4[1];
        acc[0] += xv * wa.x; acc[1] += xv * wa.y;
        acc[2] += xv * wa.z; acc[3] += xv * wa.w;
        acc[4] += xv * wb.x; acc[5] += xv * wb.y;
        acc[6] += xv * wb.z; acc[7] += xv * wb.w;
    }
#pragma unroll
    for (int e = 0; e < NEXP; e++) {
#pragma unroll
        for (int off = 16; off > 0; off >>= 1)
            acc[e] += __shfl_xor_sync(0xffffffff, acc[e], off);
    }

    if (lane == 0) {
        float lg[NEXP];
        float mx = -1e30f;
#pragma unroll
        for (int e = 0; e < NEXP; e++) {
            lg[e] = acc[e] + bg[e];
            mx = fmaxf(mx, lg[e]);
        }
        float s = 0.f;
#pragma unroll
        for (int e = 0; e < NEXP; e++) {
            lg[e] = expf(lg[e] - mx);
            s += lg[e];
        }
        float inv = 1.f / s;

        int i0 = 0; float v0 = -1.f;
#pragma unroll
        for (int e = 0; e < NEXP; e++) {
            float p = lg[e] * inv;
            if (p > v0) { v0 = p; i0 = e; }
        }
        int i1 = -1; float v1 = -1.f;
#pragma unroll
        for (int e = 0; e < NEXP; e++) {
            if (e == i0) continue;
            float p = lg[e] * inv;
            if (p > v1) { v1 = p; i1 = e; }
        }
        int p0 = atomicAdd(&g_cursor[i0], 1);
        g_token[i0 * N_TOK + p0] = n;
        g_gate [i0 * N_TOK + p0] = v0;
        g_slot [n] = i0 * N_TOK + p0;
        int p1 = atomicAdd(&g_cursor[i1], 1);
        g_token[i1 * N_TOK + p1] = n;
        g_gate [i1 * N_TOK + p1] = v1;
        g_slot [N_TOK + n] = i1 * N_TOK + p1;
    }
}

// ---------------------------------------------------------------------------
// gemm12: fused layer1+layer2 per CTA (128 tokens, full HID=256).
// Phase 1 (x2 n-halves): h1 = relu(gather(x) @ W1[e] + b1) -> smem tile 128x256
// Phase 2 (x2 n-halves): h2 = relu(h1_smem @ W2[e] + b2)   -> g_h2h
// 8 warps (4m x 2n), warptile 32x64, register-staged double buffering.
// ---------------------------------------------------------------------------
#define SM12_BYTES ((2 * BM * LDA + 2 * BM * LDB + BM * LDH1) * 2)

__global__ void __launch_bounds__(256)
gemm12_kernel(const float* __restrict__ x,
              const __half* __restrict__ W1t, const float* __restrict__ b1,
              const __half* __restrict__ W2t, const float* __restrict__ b2,
              __half* __restrict__ h2out) {
    int e = blockIdx.z;
    int count = g_cursor[e];
    int m0 = blockIdx.x * BM;
    if (m0 >= count) return;

    extern __shared__ __align__(16) __half sm12[];
    __half* As = sm12;                           // 2 x BM*LDA
    __half* Bs = sm12 + 2 * BM * LDA;            // 2 x BM*LDB
    __half* H1 = sm12 + 2 * BM * LDA + 2 * BM * LDB;  // BM x LDH1
    __shared__ int rows[BM];

    int t = threadIdx.x;
    int lane = t & 31;
    int w = t >> 5;
    int wm = w & 3;
    int wn = w >> 2;

    if (t < BM) {
        int pos = m0 + t;
        if (pos >= count) pos = count - 1;
        rows[t] = g_token[e * N_TOK + pos];
    }
    __syncthreads();

    int lr[2], lseg[2];
#pragma unroll
    for (int q = 0; q < 2; q++) {
        int s = t + 256 * q;
        lr[q] = s >> 2;
        lseg[q] = (s & 3) * 8;
    }
    const float* xsrc[2];
#pragma unroll
    for (int q = 0; q < 2; q++) xsrc[q] = x + (size_t)rows[lr[q]] * DIM;

    unsigned asb[2], bsb[2], h1b;
    asb[0] = s2u(As); asb[1] = s2u(As + BM * LDA);
    bsb[0] = s2u(Bs); bsb[1] = s2u(Bs + BM * LDB);
    h1b = s2u(H1);
    int rsel = lane & 15;
    int ksel = (lane >> 4) * 8;
    int gg = lane >> 2;
    int tc = lane & 3;

    const __half* W1e = W1t + (size_t)e * DIM * HID;
    const __half* W2e = W2t + (size_t)e * HID * HID;

    float c[2][8][4];
    uint4 va[2], vb[2];

    // ================= PHASE 1: h1 tile into smem =================
    for (int nh = 0; nh < 2; nh++) {
        int n0 = nh * 128;
        const __half* bsrc[2];
#pragma unroll
        for (int q = 0; q < 2; q++) bsrc[q] = W1e + (size_t)(n0 + lr[q]) * DIM;

#pragma unroll
        for (int mi = 0; mi < 2; mi++)
#pragma unroll
            for (int ni = 0; ni < 8; ni++)
#pragma unroll
                for (int r = 0; r < 4; r++) c[mi][ni][r] = 0.f;

        // prologue: load + store tile 0
#pragma unroll
        for (int q = 0; q < 2; q++) {
            float4 v0 = *(const float4*)(xsrc[q] + lseg[q]);
            float4 v1 = *(const float4*)(xsrc[q] + lseg[q] + 4);
            va[q].x = pack_h2(v0.x, v0.y); va[q].y = pack_h2(v0.z, v0.w);
            va[q].z = pack_h2(v1.x, v1.y); va[q].w = pack_h2(v1.z, v1.w);
            vb[q] = *(const uint4*)(bsrc[q] + lseg[q]);
            *(uint4*)&As[lr[q] * LDA + lseg[q]] = va[q];
            *(uint4*)&Bs[lr[q] * LDB + lseg[q]] = vb[q];
        }
        __syncthreads();

        const int NK = DIM / BK;  // 32
        for (int kt = 0; kt < NK; kt++) {
            int cur = kt & 1;
            if (kt + 1 < NK) {
                int k0 = (kt + 1) * BK;
#pragma unroll
                for (int q = 0; q < 2; q++) {
                    float4 v0 = *(const float4*)(xsrc[q] + k0 + lseg[q]);
                    float4 v1 = *(const float4*)(xsrc[q] + k0 + lseg[q] + 4);
                    va[q].x = pack_h2(v0.x, v0.y); va[q].y = pack_h2(v0.z, v0.w);
                    va[q].z = pack_h2(v1.x, v1.y); va[q].w = pack_h2(v1.z, v1.w);
                    vb[q] = *(const uint4*)(bsrc[q] + k0 + lseg[q]);
                }
            }
#pragma unroll
            for (int ka = 0; ka < BK; ka += 16) {
                unsigned afrag[2][4], bfrag[4][4];
#pragma unroll
                for (int mi = 0; mi < 2; mi++) {
                    unsigned addr = asb[cur] +
                        ((wm * 32 + mi * 16 + rsel) * LDA + ka + ksel) * 2;
                    ldsm_x4(addr, afrag[mi]);
                }
#pragma unroll
                for (int p = 0; p < 4; p++) {
                    unsigned addr = bsb[cur] +
                        ((wn * 64 + p * 16 + rsel) * LDB + ka + ksel) * 2;
                    ldsm_x4(addr, bfrag[p]);
                }
#pragma unroll
                for (int mi = 0; mi < 2; mi++) {
#pragma unroll
                    for (int p = 0; p < 4; p++) {
                        mma_f16(c[mi][2 * p + 0], afrag[mi], bfrag[p][0], bfrag[p][2]);
                        mma_f16(c[mi][2 * p + 1], afrag[mi], bfrag[p][1], bfrag[p][3]);
                    }
                }
            }
            if (kt + 1 < NK) {
                int nb = (kt + 1) & 1;
#pragma unroll
                for (int q = 0; q < 2; q++) {
                    *(uint4*)&As[nb * BM * LDA + lr[q] * LDA + lseg[q]] = va[q];
                    *(uint4*)&Bs[nb * BM * LDB + lr[q] * LDB + lseg[q]] = vb[q];
                }
            }
            __syncthreads();
        }

        // epilogue -> H1 smem (bias+relu, half)
        const float* be = b1 + (size_t)e * HID;
#pragma unroll
        for (int mi = 0; mi < 2; mi++) {
#pragma unroll
            for (int h = 0; h < 2; h++) {
                int m_local = wm * 32 + mi * 16 + gg + h * 8;
#pragma unroll
                for (int ni = 0; ni < 8; ni++) {
                    int col = n0 + wn * 64 + ni * 8 + tc * 2;
                    float2 bv = *(const float2*)(be + col);
                    float o0 = fmaxf(c[mi][ni][h * 2 + 0] + bv.x, 0.f);
                    float o1 = fmaxf(c[mi][ni][h * 2 + 1] + bv.y, 0.f);
                    *(unsigned*)&H1[m_local * LDH1 + col] = pack_h2(o0, o1);
                }
            }
        }
    }
    __syncthreads();  // H1 complete

    // ================= PHASE 2: h2 = relu(H1 @ W2 + b2) =================
    for (int nh = 0; nh < 2; nh++) {
        int n0 = nh * 128;
        const __half* bsrc[2];
#pragma unroll
        for (int q = 0; q < 2; q++) bsrc[q] = W2e + (size_t)(n0 + lr[q]) * HID;

#pragma unroll
        for (int mi = 0; mi < 2; mi++)
#pragma unroll
            for (int ni = 0; ni < 8; ni++)
#pragma unroll
                for (int r = 0; r < 4; r++) c[mi][ni][r] = 0.f;

#pragma unroll
        for (int q = 0; q < 2; q++) {
            vb[q] = *(const uint4*)(bsrc[q] + lseg[q]);
            *(uint4*)&Bs[lr[q] * LDB + lseg[q]] = vb[q];
        }
        __syncthreads();

        const int NK2 = HID / BK;  // 8
        for (int kt = 0; kt < NK2; kt++) {
            int cur = kt & 1;
            if (kt + 1 < NK2) {
                int k0 = (kt + 1) * BK;
#pragma unroll
                for (int q = 0; q < 2; q++)
                    vb[q] = *(const uint4*)(bsrc[q] + k0 + lseg[q]);
            }
#pragma unroll
            for (int ka = 0; ka < BK; ka += 16) {
                int kg = kt * BK + ka;
                unsigned afrag[2][4], bfrag[4][4];
#pragma unroll
                for (int mi = 0; mi < 2; mi++) {
                    unsigned addr = h1b +
                        ((wm * 32 + mi * 16 + rsel) * LDH1 + kg + ksel) * 2;
                    ldsm_x4(addr, afrag[mi]);
                }
#pragma unroll
                for (int p = 0; p < 4; p++) {
                    unsigned addr = bsb[cur] +
                        ((wn * 64 + p * 16 + rsel) * LDB + ka + ksel) * 2;
                    ldsm_x4(addr, bfrag[p]);
                }
#pragma unroll
                for (int mi = 0; mi < 2; mi++) {
#pragma unroll
                    for (int p = 0; p < 4; p++) {
                        mma_f16(c[mi][2 * p + 0], afrag[mi], bfrag[p][0], bfrag[p][2]);
                        mma_f16(c[mi][2 * p + 1], afrag[mi], bfrag[p][1], bfrag[p][3]);
                    }
                }
            }
            if (kt + 1 < NK2) {
                int nb = (kt + 1) & 1;
#pragma unroll
                for (int q = 0; q < 2; q++)
                    *(uint4*)&Bs[nb * BM * LDB + lr[q] * LDB + lseg[q]] = vb[q];
            }
            __syncthreads();
        }

        // epilogue -> gmem h2
        const float* be = b2 + (size_t)e * HID;
#pragma unroll
        for (int mi = 0; mi < 2; mi++) {
#pragma unroll
            for (int h = 0; h < 2; h++) {
                int m_local = wm * 32 + mi * 16 + gg + h * 8;
                int pos = m0 + m_local;
                if (pos < count) {
                    size_t orow = ((size_t)e * N_TOK + pos) * HID;
#pragma unroll
                    for (int ni = 0; ni < 8; ni++) {
                        int col = n0 + wn * 64 + ni * 8 + tc * 2;
                        float2 bv = *(const float2*)(be + col);
                        float o0 = fmaxf(c[mi][ni][h * 2 + 0] + bv.x, 0.f);
                        float o1 = fmaxf(c[mi][ni][h * 2 + 1] + bv.y, 0.f);
                        *(unsigned*)(h2out + orow + col) = pack_h2(o0, o1);
                    }
                }
            }
        }
    }
}

// ---------------------------------------------------------------------------
// gemm3: eo = gate * relu(h2 @ W3[e] + b3), tile 128x128, same machinery.
// ---------------------------------------------------------------------------
__global__ void __launch_bounds__(256)
gemm3_kernel(const __half* __restrict__ Ah,
             const __half* __restrict__ Bt,
             const float* __restrict__ bias,
             __half* __restrict__ Out) {
    int e = blockIdx.z;
    int count = g_cursor[e];
    int m0 = blockIdx.x * BM;
    if (m0 >= count) return;
    int n0 = blockIdx.y * BM;

    __shared__ __align__(16) __half As[2][BM * LDA];
    __shared__ __align__(16) __half Bs[2][BM * LDB];

    int t = threadIdx.x;
    int lane = t & 31;
    int w = t >> 5;
    int wm = w & 3;
    int wn = w >> 2;

    const __half* A_e = Ah + (size_t)e * N_TOK * HID;
    const __half* B_e = Bt + (size_t)e * (size_t)HID * DIM;

    int lr[2], lseg[2];
#pragma unroll
    for (int q = 0; q < 2; q++) {
        int s = t + 256 * q;
        lr[q] = s >> 2;
        lseg[q] = (s & 3) * 8;
    }
    const __half* asrc[2];
    const __half* bsrc[2];
#pragma unroll
    for (int q = 0; q < 2; q++) {
        asrc[q] = A_e + (size_t)(m0 + lr[q]) * HID;
        bsrc[q] = B_e + (size_t)(n0 + lr[q]) * HID;
    }

    uint4 va[2], vb[2];
    unsigned asb[2], bsb[2];
#pragma unroll
    for (int b = 0; b < 2; b++) {
        asb[b] = s2u(&As[b][0]);
        bsb[b] = s2u(&Bs[b][0]);
    }
    int rsel = lane & 15;
    int ksel = (lane >> 4) * 8;

    float c[2][8][4];
#pragma unroll
    for (int mi = 0; mi < 2; mi++)
#pragma unroll
        for (int ni = 0; ni < 8; ni++)
#pragma unroll
            for (int r = 0; r < 4; r++) c[mi][ni][r] = 0.f;

    const int NK = HID / BK;  // 8
#pragma unroll
    for (int q = 0; q < 2; q++) {
        va[q] = *(const uint4*)(asrc[q] + lseg[q]);
        vb[q] = *(const uint4*)(bsrc[q] + lseg[q]);
        *(uint4*)&As[0][lr[q] * LDA + lseg[q]] = va[q];
        *(uint4*)&Bs[0][lr[q] * LDB + lseg[q]] = vb[q];
    }
    __syncthreads();

    for (int kt = 0; kt < NK; kt++) {
        int cur = kt & 1;
        if (kt + 1 < NK) {
            int k0 = (kt + 1) * BK;
#pragma unroll
            for (int q = 0; q < 2; q++) {
                va[q] = *(const uint4*)(asrc[q] + k0 + lseg[q]);
                vb[q] = *(const uint4*)(bsrc[q] + k0 + lseg[q]);
            }
        }
#pragma unroll
        for (int ka = 0; ka < BK; ka += 16) {
            unsigned afrag[2][4], bfrag[4][4];
#pragma unroll
            for (int mi = 0; mi < 2; mi++) {
                unsigned addr = asb[cur] +
                    ((wm * 32 + mi * 16 + rsel) * LDA + ka + ksel) * 2;
                ldsm_x4(addr, afrag[mi]);
            }
#pragma unroll
            for (int p = 0; p < 4; p++) {
                unsigned addr = bsb[cur] +
                    ((wn * 64 + p * 16 + rsel) * LDB + ka + ksel) * 2;
                ldsm_x4(addr, bfrag[p]);
            }
#pragma unroll
            for (int mi = 0; mi < 2; mi++) {
#pragma unroll
                for (int p = 0; p < 4; p++) {
                    mma_f16(c[mi][2 * p + 0], afrag[mi], bfrag[p][0], bfrag[p][2]);
                    mma_f16(c[mi][2 * p + 1], afrag[mi], bfrag[p][1], bfrag[p][3]);
                }
            }
        }
        if (kt + 1 < NK) {
            int nb = (kt + 1) & 1;
#pragma unroll
            for (int q = 0; q < 2; q++) {
                *(uint4*)&As[nb][lr[q] * LDA + lseg[q]] = va[q];
                *(uint4*)&Bs[nb][lr[q] * LDB + lseg[q]] = vb[q];
            }
        }
        __syncthreads();
    }

    const float* bias_e = bias + (size_t)e * DIM;
    int gg = lane >> 2;
    int tc = lane & 3;
#pragma unroll
    for (int mi = 0; mi < 2; mi++) {
#pragma unroll
        for (int h = 0; h < 2; h++) {
            int m_local = wm * 32 + mi * 16 + gg + h * 8;
            int pos = m0 + m_local;
            if (pos < count) {
                float gate = g_gate[e * N_TOK + pos];
                size_t orow = ((size_t)e * N_TOK + pos) * DIM;
#pragma unroll
                for (int ni = 0; ni < 8; ni++) {
                    int n = n0 + wn * 64 + ni * 8 + tc * 2;
                    float2 bv = *(const float2*)(bias_e + n);
                    float o0 = gate * fmaxf(c[mi][ni][h * 2 + 0] + bv.x, 0.f);
                    float o1 = gate * fmaxf(c[mi][ni][h * 2 + 1] + bv.y, 0.f);
                    *(unsigned*)(Out + orow + n) = pack_h2(o0, o1);
                }
            }
        }
    }
}

// ---------------------------------------------------------------------------
// combine: out[n,:] = eo[slot0[n],:] + eo[slot1[n],:]  (half -> fp32)
// ---------------------------------------------------------------------------
__global__ void combine_kernel(float* __restrict__ out) {
    const __half* eo = g_eoh;
    int tot = N_TOK * (DIM / 8);
    int stride = gridDim.x * blockDim.x;
    for (int idx = blockIdx.x * blockDim.x + threadIdx.x; idx < tot; idx += stride) {
        int n = idx >> 7;           // DIM/8 = 128
        int cidx = (idx & 127) * 8;
        int s0 = g_slot[n];
        int s1 = g_slot[N_TOK + n];
        uint4 a4 = *(const uint4*)(eo + (size_t)s0 * DIM + cidx);
        uint4 b4 = *(const uint4*)(eo + (size_t)s1 * DIM + cidx);
        const __half2* ah = (const __half2*)&a4;
        const __half2* bh = (const __half2*)&b4;
        float4 o0, o1;
        float2 t0 = __half22float2(ah[0]), u0 = __half22float2(bh[0]);
        float2 t1 = __half22float2(ah[1]), u1 = __half22float2(bh[1]);
        float2 t2 = __half22float2(ah[2]), u2 = __half22float2(bh[2]);
        float2 t3 = __half22float2(ah[3]), u3 = __half22float2(bh[3]);
        o0.x = t0.x + u0.x; o0.y = t0.y + u0.y;
        o0.z = t1.x + u1.x; o0.w = t1.y + u1.y;
        o1.x = t2.x + u2.x; o1.y = t2.y + u2.y;
        o1.z = t3.x + u3.x; o1.w = t3.y + u3.y;
        float* op = out + (size_t)n * DIM + cidx;
        *(float4*)(op + 0) = o0;
        *(float4*)(op + 4) = o1;
    }
}

// ---------------------------------------------------------------------------
extern "C" void kernel_launch(void* const* d_in, const int* in_sizes, int n_in,
                              void* d_out, int out_size) {
    const float* x  = (const float*)d_in[0];
    const float* Wg = (const float*)d_in[1];
    const float* bg = (const float*)d_in[2];
    const float* W1 = (const float*)d_in[3];
    const float* b1 = (const float*)d_in[4];
    const float* W2 = (const float*)d_in[5];
    const float* b2 = (const float*)d_in[6];
    const float* W3 = (const float*)d_in[7];
    const float* b3 = (const float*)d_in[8];
    float* out = (float*)d_out;

    __half *h2, *eo, *w1t, *w2t, *w3t;
    cudaGetSymbolAddress((void**)&h2,  g_h2h);
    cudaGetSymbolAddress((void**)&eo,  g_eoh);
    cudaGetSymbolAddress((void**)&w1t, g_w1t);
    cudaGetSymbolAddress((void**)&w2t, g_w2t);
    cudaGetSymbolAddress((void**)&w3t, g_w3t);

    cudaFuncSetAttribute(gemm12_kernel,
                         cudaFuncAttributeMaxDynamicSharedMemorySize, SM12_BYTES);

    prep_kernel<<<dim3(288, 1, NEXP), 256>>>(W1, W2, W3, w1t, w2t, w3t);
    gating_kernel<<<N_TOK / 8, 256>>>(x, Wg, bg);
    gemm12_kernel<<<dim3(N_TOK / BM, 1, NEXP), 256, SM12_BYTES>>>(
        x, w1t, b1, w2t, b2, h2);
    gemm3_kernel<<<dim3(N_TOK / BM, DIM / BM, NEXP), 256>>>(h2, w3t, b3, eo);
    combine_kernel<<<2048, 256>>>(out);
}

// round 12
// speedup vs baseline: 1.4221x; 1.4221x over previous
#include <cuda_runtime.h>
#include <cuda_fp16.h>
#include <cstdint>

#define N_TOK 8192
#define DIM   1024
#define NEXP  8
#define HID   256

#define BM 128
#define BN 128
#define BK 32    // K elements per tile (2 x k16 mma steps)
#define LDA 40   // padded row stride in halves: 80B, conflict-free ldmatrix
#define LDB 40

// ---- static device scratch (no allocations allowed) ----
__device__ int    g_cursor[NEXP];
__device__ int    g_token[NEXP * N_TOK];
__device__ float  g_gate [NEXP * N_TOK];
__device__ int    g_dst  [NEXP * N_TOK];               // eo row = 2*token+which
__device__ __half g_h1h[(size_t)NEXP * N_TOK * HID];   // 32 MB
__device__ __half g_h2h[(size_t)NEXP * N_TOK * HID];   // 32 MB
__device__ __half g_eoh[(size_t)2 * N_TOK * DIM];      // 32 MB token-major
__device__ __half g_w1t[(size_t)NEXP * DIM * HID];     // 4 MB  [e][N][K] half
__device__ __half g_w2t[(size_t)NEXP * HID * HID];     // 1 MB
__device__ __half g_w3t[(size_t)NEXP * HID * DIM];     // 4 MB

// ---------------------------------------------------------------------------
__device__ __forceinline__ void ldsm_x4(unsigned addr, unsigned r[4]) {
    asm volatile("ldmatrix.sync.aligned.m8n8.x4.shared.b16 {%0,%1,%2,%3}, [%4];"
                 : "=r"(r[0]), "=r"(r[1]), "=r"(r[2]), "=r"(r[3]) : "r"(addr));
}
__device__ __forceinline__ void mma_f16(float c[4], const unsigned a[4],
                                        unsigned b0, unsigned b1) {
    asm volatile(
        "mma.sync.aligned.m16n8k16.row.col.f32.f16.f16.f32 "
        "{%0,%1,%2,%3}, {%4,%5,%6,%7}, {%8,%9}, {%0,%1,%2,%3};"
        : "+f"(c[0]), "+f"(c[1]), "+f"(c[2]), "+f"(c[3])
        : "r"(a[0]), "r"(a[1]), "r"(a[2]), "r"(a[3]), "r"(b0), "r"(b1));
}
__device__ __forceinline__ unsigned pack_h2(float x, float y) {
    __half2 h = __floats2half2_rn(x, y);
    return *(unsigned*)&h;
}

// ---------------------------------------------------------------------------
// prep: zero cursors + transpose/convert weights to [e][N][K] half
// ---------------------------------------------------------------------------
__global__ void prep_kernel(const float* __restrict__ W1,
                            const float* __restrict__ W2,
                            const float* __restrict__ W3,
                            __half* __restrict__ w1t,
                            __half* __restrict__ w2t,
                            __half* __restrict__ w3t) {
    if (blockIdx.x == 0 && blockIdx.z == 0 && threadIdx.x < NEXP)
        g_cursor[threadIdx.x] = 0;

    int e = blockIdx.z;
    int bid = blockIdx.x;
    const float* src;
    __half* dst;
    int KD, ND, kt, nt;
    if (bid < 128) {
        src = W1 + (size_t)e * DIM * HID; dst = w1t + (size_t)e * DIM * HID;
        KD = DIM; ND = HID; kt = bid >> 3; nt = bid & 7;
    } else if (bid < 160) {
        int r = bid - 128;
        src = W2 + (size_t)e * HID * HID; dst = w2t + (size_t)e * HID * HID;
        KD = HID; ND = HID; kt = r >> 3; nt = r & 7;
    } else {
        int r = bid - 160;
        src = W3 + (size_t)e * HID * DIM; dst = w3t + (size_t)e * HID * DIM;
        KD = HID; ND = DIM; kt = r >> 5; nt = r & 31;
    }

    __shared__ float tile[64][33];
    int tx = threadIdx.x & 31, ty = threadIdx.x >> 5;
    int k0 = kt * 64, n0 = nt * 32;
#pragma unroll
    for (int kr = ty; kr < 64; kr += 8)
        tile[kr][tx] = src[(size_t)(k0 + kr) * ND + n0 + tx];
    __syncthreads();
#pragma unroll
    for (int nr = ty; nr < 32; nr += 8) {
        __half2 hv = __floats2half2_rn(tile[2 * tx][nr], tile[2 * tx + 1][nr]);
        *(__half2*)(dst + (size_t)(n0 + nr) * KD + k0 + 2 * tx) = hv;
    }
}

// ---------------------------------------------------------------------------
// gating: one warp per token (uses ORIGINAL fp32 x)
// ---------------------------------------------------------------------------
__global__ void gating_kernel(const float* __restrict__ x,
                              const float* __restrict__ Wg,
                              const float* __restrict__ bg) {
    int warp = threadIdx.x >> 5;
    int lane = threadIdx.x & 31;
    int n = blockIdx.x * 8 + warp;
    if (n >= N_TOK) return;

    float acc[NEXP];
#pragma unroll
    for (int e = 0; e < NEXP; e++) acc[e] = 0.f;

    const float* xr = x + (size_t)n * DIM;
    for (int d = lane; d < DIM; d += 32) {
        float xv = xr[d];
        const float4* w4 = (const float4*)(Wg + (size_t)d * NEXP);
        float4 wa = w4[0];
        float4 wb = w4[1];
        acc[0] += xv * wa.x; acc[1] += xv * wa.y;
        acc[2] += xv * wa.z; acc[3] += xv * wa.w;
        acc[4] += xv * wb.x; acc[5] += xv * wb.y;
        acc[6] += xv * wb.z; acc[7] += xv * wb.w;
    }
#pragma unroll
    for (int e = 0; e < NEXP; e++) {
#pragma unroll
        for (int off = 16; off > 0; off >>= 1)
            acc[e] += __shfl_xor_sync(0xffffffff, acc[e], off);
    }

    if (lane == 0) {
        float lg[NEXP];
        float mx = -1e30f;
#pragma unroll
        for (int e = 0; e < NEXP; e++) {
            lg[e] = acc[e] + bg[e];
            mx = fmaxf(mx, lg[e]);
        }
        float s = 0.f;
#pragma unroll
        for (int e = 0; e < NEXP; e++) {
            lg[e] = expf(lg[e] - mx);
            s += lg[e];
        }
        float inv = 1.f / s;

        int i0 = 0; float v0 = -1.f;
#pragma unroll
        for (int e = 0; e < NEXP; e++) {
            float p = lg[e] * inv;
            if (p > v0) { v0 = p; i0 = e; }
        }
        int i1 = -1; float v1 = -1.f;
#pragma unroll
        for (int e = 0; e < NEXP; e++) {
            if (e == i0) continue;
            float p = lg[e] * inv;
            if (p > v1) { v1 = p; i1 = e; }
        }
        int p0 = atomicAdd(&g_cursor[i0], 1);
        g_token[i0 * N_TOK + p0] = n;
        g_gate [i0 * N_TOK + p0] = v0;
        g_dst  [i0 * N_TOK + p0] = 2 * n;
        int p1 = atomicAdd(&g_cursor[i1], 1);
        g_token[i1 * N_TOK + p1] = n;
        g_gate [i1 * N_TOK + p1] = v1;
        g_dst  [i1 * N_TOK + p1] = 2 * n + 1;
    }
}

// ---------------------------------------------------------------------------
// fp16 HMMA GEMM: CTA tile 128x128xK, 8 warps (4m x 2n), warptile 32x64.
// m16n8k16.f32.f16.f16.f32, register-staged double-buffered smem.
//   MODE 0: A = x fp32 gathered by g_token (cvt inline) -> g_h1h (relu, half)
//   MODE 1: A = g_h1h                                   -> g_h2h (relu, half)
//   MODE 2: A = g_h2h                                   -> g_eoh[g_dst] (gate*relu)
// ---------------------------------------------------------------------------
template <int KDIM, int NMAT, int MODE>
__global__ void __launch_bounds__(256)
gemm_mma(const float* __restrict__ Af,      // fp32 source (MODE 0)
         const __half* __restrict__ Ah,     // half source (MODE 1/2)
         const __half* __restrict__ Bt,     // [e][NMAT][KDIM] half weights
         const float* __restrict__ bias,
         __half* __restrict__ Out) {
    int e = blockIdx.z;
    int count = g_cursor[e];
    int m0 = blockIdx.x * BM;
    if (m0 >= count) return;
    int n0 = blockIdx.y * BN;

    __shared__ __align__(16) __half As[2][BM * LDA];
    __shared__ __align__(16) __half Bs[2][BN * LDB];
    __shared__ int rows[BM];

    int t = threadIdx.x;
    int lane = t & 31;
    int w = t >> 5;
    int wm = w & 3;
    int wn = w >> 2;

    const __half* A_eh = Ah + (size_t)e * N_TOK * HID;
    const __half* B_e  = Bt + (size_t)e * (size_t)KDIM * NMAT;

    if (MODE == 0 && t < BM) {
        int pos = m0 + t;
        if (pos >= count) pos = count - 1;
        rows[t] = g_token[e * N_TOK + pos];
    }
    __syncthreads();

    // per-thread load tasks: 512 16B-segs (8 halves) each for A and B, 2/thr
    int a_row[2], a_seg[2];
#pragma unroll
    for (int q = 0; q < 2; q++) {
        int s = t + 256 * q;
        a_row[q] = s >> 2;          // 0..127
        a_seg[q] = (s & 3) * 8;     // half-offset within 32-half row chunk
    }
    const float*  a_srcf[2];
    const __half* a_srch[2];
    const __half* b_src [2];
#pragma unroll
    for (int q = 0; q < 2; q++) {
        if (MODE == 0) a_srcf[q] = Af + (size_t)rows[a_row[q]] * KDIM;
        else           a_srch[q] = A_eh + (size_t)(m0 + a_row[q]) * KDIM;
        b_src[q] = B_e + (size_t)(n0 + a_row[q]) * KDIM;
    }

    uint4 va[2], vb[2];
    auto load_regs = [&](int kt) {
        int k0 = kt * BK;
#pragma unroll
        for (int q = 0; q < 2; q++) {
            if (MODE == 0) {
                float4 v0 = *(const float4*)(a_srcf[q] + k0 + a_seg[q]);
                float4 v1 = *(const float4*)(a_srcf[q] + k0 + a_seg[q] + 4);
                va[q].x = pack_h2(v0.x, v0.y);
                va[q].y = pack_h2(v0.z, v0.w);
                va[q].z = pack_h2(v1.x, v1.y);
                va[q].w = pack_h2(v1.z, v1.w);
            } else {
                va[q] = *(const uint4*)(a_srch[q] + k0 + a_seg[q]);
            }
            vb[q] = *(const uint4*)(b_src[q] + k0 + a_seg[q]);
        }
    };
    auto store_smem = [&](int buf) {
#pragma unroll
        for (int q = 0; q < 2; q++) {
            *(uint4*)&As[buf][a_row[q] * LDA + a_seg[q]] = va[q];
            *(uint4*)&Bs[buf][a_row[q] * LDB + a_seg[q]] = vb[q];
        }
    };

    unsigned asb[2], bsb[2];
#pragma unroll
    for (int b = 0; b < 2; b++) {
        asb[b] = (unsigned)__cvta_generic_to_shared(&As[b][0]);
        bsb[b] = (unsigned)__cvta_generic_to_shared(&Bs[b][0]);
    }
    int rsel = lane & 15;
    int ksel = (lane >> 4) * 8;

    float c[2][8][4];
#pragma unroll
    for (int mi = 0; mi < 2; mi++)
#pragma unroll
        for (int ni = 0; ni < 8; ni++)
#pragma unroll
            for (int r = 0; r < 4; r++) c[mi][ni][r] = 0.f;

    const int NK = KDIM / BK;
    load_regs(0);
    store_smem(0);
    __syncthreads();

    for (int kt = 0; kt < NK; kt++) {
        int cur = kt & 1;
        if (kt + 1 < NK) load_regs(kt + 1);

#pragma unroll
        for (int ka = 0; ka < BK; ka += 16) {
            unsigned afrag[2][4], bfrag[4][4];
#pragma unroll
            for (int mi = 0; mi < 2; mi++) {
                unsigned addr = asb[cur] +
                    ((wm * 32 + mi * 16 + rsel) * LDA + ka + ksel) * 2;
                ldsm_x4(addr, afrag[mi]);
            }
#pragma unroll
            for (int p = 0; p < 4; p++) {
                unsigned addr = bsb[cur] +
                    ((wn * 64 + p * 16 + rsel) * LDB + ka + ksel) * 2;
                ldsm_x4(addr, bfrag[p]);
            }
#pragma unroll
            for (int mi = 0; mi < 2; mi++) {
#pragma unroll
                for (int p = 0; p < 4; p++) {
                    mma_f16(c[mi][2 * p + 0], afrag[mi], bfrag[p][0], bfrag[p][2]);
                    mma_f16(c[mi][2 * p + 1], afrag[mi], bfrag[p][1], bfrag[p][3]);
                }
            }
        }

        if (kt + 1 < NK) store_smem((kt + 1) & 1);
        __syncthreads();
    }

    // ---- epilogue: packed half2 stores ----
    const float* bias_e = bias + (size_t)e * NMAT;
    int gg = lane >> 2;
    int tc = lane & 3;

#pragma unroll
    for (int mi = 0; mi < 2; mi++) {
#pragma unroll
        for (int h = 0; h < 2; h++) {
            int m_local = wm * 32 + mi * 16 + gg + h * 8;
            int pos = m0 + m_local;
            if (pos < count) {
                float gate = 1.f;
                size_t orow;
                if (MODE == 2) {
                    gate = g_gate[e * N_TOK + pos];
                    orow = (size_t)g_dst[e * N_TOK + pos] * DIM;
                } else {
                    orow = ((size_t)e * N_TOK + pos) * HID;
                }
#pragma unroll
                for (int ni = 0; ni < 8; ni++) {
                    int n = n0 + wn * 64 + ni * 8 + tc * 2;
                    float v0 = c[mi][ni][h * 2 + 0];
                    float v1 = c[mi][ni][h * 2 + 1];
                    float2 bv = *(const float2*)(bias_e + n);
                    float o0, o1;
                    if (MODE == 2) {
                        o0 = gate * fmaxf(v0 + bv.x, 0.f);
                        o1 = gate * fmaxf(v1 + bv.y, 0.f);
                    } else {
                        o0 = fmaxf(v0 + bv.x, 0.f);
                        o1 = fmaxf(v1 + bv.y, 0.f);
                    }
                    *(unsigned*)(Out + orow + n) = pack_h2(o0, o1);
                }
            }
        }
    }
}

// ---------------------------------------------------------------------------
// combine: out[n,:] = eo[2n,:] + eo[2n+1,:]  (token-major, pure streaming)
// ---------------------------------------------------------------------------
__global__ void combine_kernel(float* __restrict__ out) {
    const __half* eo = g_eoh;
    int tot = N_TOK * (DIM / 8);
    int stride = gridDim.x * blockDim.x;
    for (int idx = blockIdx.x * blockDim.x + threadIdx.x; idx < tot; idx += stride) {
        int n = idx >> 7;           // DIM/8 = 128
        int cidx = (idx & 127) * 8;
        uint4 a4 = *(const uint4*)(eo + (size_t)(2 * n)     * DIM + cidx);
        uint4 b4 = *(const uint4*)(eo + (size_t)(2 * n + 1) * DIM + cidx);
        const __half2* ah = (const __half2*)&a4;
        const __half2* bh = (const __half2*)&b4;
        float4 o0, o1;
        float2 t0 = __half22float2(ah[0]), u0 = __half22float2(bh[0]);
        float2 t1 = __half22float2(ah[1]), u1 = __half22float2(bh[1]);
        float2 t2 = __half22float2(ah[2]), u2 = __half22float2(bh[2]);
        float2 t3 = __half22float2(ah[3]), u3 = __half22float2(bh[3]);
        o0.x = t0.x + u0.x; o0.y = t0.y + u0.y;
        o0.z = t1.x + u1.x; o0.w = t1.y + u1.y;
        o1.x = t2.x + u2.x; o1.y = t2.y + u2.y;
        o1.z = t3.x + u3.x; o1.w = t3.y + u3.y;
        float* op = out + (size_t)n * DIM + cidx;
        *(float4*)(op + 0) = o0;
        *(float4*)(op + 4) = o1;
    }
}

// ---------------------------------------------------------------------------
extern "C" void kernel_launch(void* const* d_in, const int* in_sizes, int n_in,
                              void* d_out, int out_size) {
    const float* x  = (const float*)d_in[0];
    const float* Wg = (const float*)d_in[1];
    const float* bg = (const float*)d_in[2];
    const float* W1 = (const float*)d_in[3];
    const float* b1 = (const float*)d_in[4];
    const float* W2 = (const float*)d_in[5];
    const float* b2 = (const float*)d_in[6];
    const float* W3 = (const float*)d_in[7];
    const float* b3 = (const float*)d_in[8];
    float* out = (float*)d_out;

    __half *h1, *h2, *eo, *w1t, *w2t, *w3t;
    cudaGetSymbolAddress((void**)&h1,  g_h1h);
    cudaGetSymbolAddress((void**)&h2,  g_h2h);
    cudaGetSymbolAddress((void**)&eo,  g_eoh);
    cudaGetSymbolAddress((void**)&w1t, g_w1t);
    cudaGetSymbolAddress((void**)&w2t, g_w2t);
    cudaGetSymbolAddress((void**)&w3t, g_w3t);

    prep_kernel<<<dim3(288, 1, NEXP), 256>>>(W1, W2, W3, w1t, w2t, w3t);
    gating_kernel<<<N_TOK / 8, 256>>>(x, Wg, bg);

    gemm_mma<DIM, HID, 0><<<dim3(N_TOK / BM, HID / BN, NEXP), 256>>>(x, h1, w1t, b1, h1);
    gemm_mma<HID, HID, 1><<<dim3(N_TOK / BM, HID / BN, NEXP), 256>>>(nullptr, h1, w2t, b2, h2);
    gemm_mma<HID, DIM, 2><<<dim3(N_TOK / BM, DIM / BN, NEXP), 256>>>(nullptr, h2, w3t, b3, eo);
    combine_kernel<<<2048, 256>>>(out);
}